// round 3
// baseline (speedup 1.0000x reference)
#include <cuda_runtime.h>
#include <math.h>

// RandomLowRes2D, two-kernel pipeline:
//   K1: Gaussian blur (31-tap, symmetric boundary) along the processed axis,
//       chunked smem stencil, writes full-res blurred image to scratch in
//       natural orientation (smem transpose for axis==1).
//   K2: fused downsample(1/res)+upsample(res) linear resample: 4 taps/output.

#define HDIM  512
#define RAD   15
#define NW    31
#define CH    128          // rows per blur chunk
#define TW    32           // cross-axis lanes per CTA
#define PITCH 33
#define NT1   256
#define UN    8            // outputs per blur task (register sliding window)

__device__ float g_s[64 * HDIM * HDIM];   // blurred full-res scratch (64 MB)

__device__ __forceinline__ int refl(int t) {
    t = (t < 0) ? (-1 - t) : t;
    return (t >= HDIM) ? (2 * HDIM - 1 - t) : t;
}

__global__ __launch_bounds__(NT1)
void blur_kernel(const float* __restrict__ x,
                 const float* __restrict__ resolution,
                 const int*   __restrict__ axis,
                 const float* __restrict__ gap)
{
    __shared__ float A[(CH + 2 * RAD) * PITCH];
    __shared__ float S[CH * PITCH];
    __shared__ float w[NW];
    __shared__ float wsum;

    const int img   = blockIdx.z;
    const int chunk = blockIdx.y;
    const int tile  = blockIdx.x;
    const int tid   = threadIdx.x;

    const float res = resolution[img];
    const int   ax  = axis[img];
    const float sig = fmaxf(res * gap[img] * 0.42466090014400953f, 1e-6f);

    if (tid < NW) {
        float e = (float)(tid - RAD) / sig;
        w[tid] = expf(-0.5f * e * e);
    }
    __syncthreads();
    if (tid == 0) {
        float s = 0.f;
        #pragma unroll
        for (int k = 0; k < NW; k++) s += w[k];
        wsum = s;
    }
    __syncthreads();
    if (tid < NW) w[tid] = w[tid] / wsum;
    // visibility of w[] ensured by the __syncthreads() after the load phase

    const int c0   = chunk * CH;
    const int base = tile * TW;
    const size_t ib = (size_t)img * HDIM * HDIM;
    const float* ip = x + ib;
    float*       sp = g_s + ib;

    // ---- load halo'd chunk into A[pos_local][lane], coalesced both axes ----
    if (ax == 0) {
        for (int idx = tid; idx < (CH + 2 * RAD) * TW; idx += NT1) {
            int lane = idx & (TW - 1);
            int r    = idx >> 5;
            A[r * PITCH + lane] = ip[refl(c0 - RAD + r) * HDIM + base + lane];
        }
    } else {
        int tx = tid & 31, ty = tid >> 5;           // warp strides along pos
        for (int p = tx; p < CH + 2 * RAD; p += 32)
            for (int lane = ty; lane < TW; lane += NT1 / 32)
                A[p * PITCH + lane] = ip[(base + lane) * HDIM + refl(c0 - RAD + p)];
    }
    __syncthreads();

    // ---- 31-tap blur via register sliding window, UN outputs per task ----
    for (int task = tid; task < (CH / UN) * TW; task += NT1) {
        int lane = task & (TW - 1);
        int p0   = (task >> 5) * UN;
        float win[UN + NW - 1];
        #pragma unroll
        for (int j = 0; j < UN + NW - 1; j++)
            win[j] = A[(p0 + j) * PITCH + lane];
        #pragma unroll
        for (int u = 0; u < UN; u++) {
            float acc = 0.f;
            #pragma unroll
            for (int k = 0; k < NW; k++) acc += w[k] * win[u + k];
            if (ax == 0)
                sp[(size_t)(c0 + p0 + u) * HDIM + base + lane] = acc;  // coalesced
            else
                S[(p0 + u) * PITCH + lane] = acc;
        }
    }

    if (ax == 1) {  // transpose-store so scratch is in natural [row][col] layout
        __syncthreads();
        int tx = tid & 31, ty = tid >> 5;
        for (int p = tx; p < CH; p += 32)
            for (int lane = ty; lane < TW; lane += NT1 / 32)
                sp[(size_t)(base + lane) * HDIM + c0 + p] = S[p * PITCH + lane];
    }
}

#define NT2 128

__global__ __launch_bounds__(NT2)
void resample_kernel(const float* __restrict__ resolution,
                     const int*   __restrict__ axis,
                     float* __restrict__ out)
{
    const int img  = blockIdx.y;
    const int line = blockIdx.x;    // output row (ax=0: i, ax=1: r)
    const int tid  = threadIdx.x;

    const float res = resolution[img];
    const int   ax  = axis[img];
    const int n_low = (int)fmaxf(floorf((float)HDIM / res), 1.0f);
    const float nl1 = (float)(n_low - 1);

    const size_t ib = (size_t)img * HDIM * HDIM;
    const float* sp = g_s + ib;
    float*       op = out + ib;

    if (ax == 0) {
        const int i = line;
        // upsample coords (same for the whole row)
        float pos2 = fminf((float)i / res, nl1);
        float l2   = floorf(pos2);
        float fr2  = pos2 - l2;
        int j1 = min((int)l2, n_low - 1);
        int j2 = min(j1 + 1, n_low - 1);
        // downsample coords for the two low rows
        float posA = fminf((float)j1 * res, 511.0f);
        float lA = floorf(posA); float frA = posA - lA;
        int p1 = (int)lA, p2 = min(p1 + 1, HDIM - 1);
        float posB = fminf((float)j2 * res, 511.0f);
        float lB = floorf(posB); float frB = posB - lB;
        int q1 = (int)lB, q2 = min(q1 + 1, HDIM - 1);

        const float4* rp1 = (const float4*)(sp + (size_t)p1 * HDIM);
        const float4* rp2 = (const float4*)(sp + (size_t)p2 * HDIM);
        const float4* rq1 = (const float4*)(sp + (size_t)q1 * HDIM);
        const float4* rq2 = (const float4*)(sp + (size_t)q2 * HDIM);
        float4*       ro  = (float4*)(op + (size_t)i * HDIM);
        for (int c = tid; c < HDIM / 4; c += NT2) {
            float4 a = rp1[c], b = rp2[c], cc = rq1[c], d = rq2[c];
            float4 r;
            float lowA, lowB;
            lowA = a.x * (1.f - frA) + b.x * frA;
            lowB = cc.x * (1.f - frB) + d.x * frB;
            r.x = lowA * (1.f - fr2) + lowB * fr2;
            lowA = a.y * (1.f - frA) + b.y * frA;
            lowB = cc.y * (1.f - frB) + d.y * frB;
            r.y = lowA * (1.f - fr2) + lowB * fr2;
            lowA = a.z * (1.f - frA) + b.z * frA;
            lowB = cc.z * (1.f - frB) + d.z * frB;
            r.z = lowA * (1.f - fr2) + lowB * fr2;
            lowA = a.w * (1.f - frA) + b.w * frA;
            lowB = cc.w * (1.f - frB) + d.w * frB;
            r.w = lowA * (1.f - fr2) + lowB * fr2;
            ro[c] = r;
        }
    } else {
        const int r = line;
        const float* row = sp + (size_t)r * HDIM;
        float*       ro  = op + (size_t)r * HDIM;
        for (int i = tid; i < HDIM; i += NT2) {
            float pos2 = fminf((float)i / res, nl1);
            float l2   = floorf(pos2);
            float fr2  = pos2 - l2;
            int j1 = min((int)l2, n_low - 1);
            int j2 = min(j1 + 1, n_low - 1);
            float posA = fminf((float)j1 * res, 511.0f);
            float lA = floorf(posA); float frA = posA - lA;
            int p1 = (int)lA, p2 = min(p1 + 1, HDIM - 1);
            float posB = fminf((float)j2 * res, 511.0f);
            float lB = floorf(posB); float frB = posB - lB;
            int q1 = (int)lB, q2 = min(q1 + 1, HDIM - 1);

            float lowA = row[p1] * (1.f - frA) + row[p2] * frA;
            float lowB = row[q1] * (1.f - frB) + row[q2] * frB;
            ro[i] = lowA * (1.f - fr2) + lowB * fr2;
        }
    }
}

extern "C" void kernel_launch(void* const* d_in, const int* in_sizes, int n_in,
                              void* d_out, int out_size)
{
    const float* x   = (const float*)d_in[0];
    const float* res = (const float*)d_in[1];
    const int*   ax  = (const int*)d_in[2];
    const float* gp  = (const float*)d_in[3];
    float* out = (float*)d_out;

    const int n_img = in_sizes[1];   // 64

    dim3 g1(HDIM / TW, HDIM / CH, n_img);   // 16 x 4 x 64
    blur_kernel<<<g1, NT1>>>(x, res, ax, gp);

    dim3 g2(HDIM, n_img);                    // 512 x 64
    resample_kernel<<<g2, NT2>>>(res, ax, out);
}

// round 4
// speedup vs baseline: 1.5914x; 1.5914x over previous
#include <cuda_runtime.h>
#include <math.h>

// RandomLowRes2D fused kernel: per-image 31-tap Gaussian blur (adaptive
// truncation, symmetric boundary) + linear down(1/res)+up(res) resample
// along one axis. 64 images of 512x512 fp32. One CTA per (img, 16-lane slab).

#define HDIM  512
#define TW    16
#define PITCH 17
#define NT    256

__device__ __forceinline__ int refl(int t) {
    t = (t < 0) ? (-1 - t) : t;
    return (t >= HDIM) ? (2 * HDIM - 1 - t) : t;
}

// Blur A -> S along pos, register-resident weights, register sliding window.
template<int R, int UN>
__device__ __forceinline__ void blur_slab(const float* __restrict__ A,
                                          float* __restrict__ S,
                                          const float* __restrict__ w,
                                          float inv_wsum, int tid)
{
    float wr[2 * R + 1];
    #pragma unroll
    for (int k = 0; k < 2 * R + 1; k++) wr[k] = w[15 - R + k] * inv_wsum;

    const int NTASK = (HDIM / UN) * TW;
    for (int task = tid; task < NTASK; task += NT) {
        int lane = task & (TW - 1);
        int p0   = (task >> 4) * UN;
        float win[UN + 2 * R];
        #pragma unroll
        for (int j = 0; j < UN + 2 * R; j++)
            win[j] = A[refl(p0 - R + j) * PITCH + lane];
        #pragma unroll
        for (int u = 0; u < UN; u++) {
            float acc = wr[0] * win[u];
            #pragma unroll
            for (int k = 1; k < 2 * R + 1; k++) acc += wr[k] * win[u + k];
            S[(p0 + u) * PITCH + lane] = acc;
        }
    }
}

__global__ __launch_bounds__(NT, 2)
void lowres_kernel(const float* __restrict__ x,
                   const float* __restrict__ resolution,
                   const int*   __restrict__ axis,
                   const float* __restrict__ gap,
                   float* __restrict__ out)
{
    extern __shared__ float dynsm[];
    float* A = dynsm;                    // [HDIM][PITCH] input slab
    float* S = dynsm + HDIM * PITCH;     // [HDIM][PITCH] blurred slab
    __shared__ float w[32];              // raw (unnormalized) Gaussian weights
    __shared__ float uf[HDIM];           // upsample frac per output i
    __shared__ int   uj[HDIM];           // upsample low-index per output i
    __shared__ float df[HDIM];           // downsample frac per low j
    __shared__ int   dp[HDIM];           // downsample src row per low j

    const int img  = blockIdx.y;
    const int tile = blockIdx.x;
    const int tid  = threadIdx.x;

    const float res = resolution[img];
    const int   ax  = axis[img];
    const float sig = fmaxf(res * gap[img] * 0.42466090014400953f, 1e-6f);

    // truncation bucket: keep taps with |k| <= R where R >= 5*sigma
    const int R = (sig < 0.18f) ? 0 : (sig < 0.6f) ? 3 : (sig < 1.4f) ? 7 : 15;

    const int   n_low = (int)fmaxf(floorf(512.0f / res), 1.0f);
    const float nl1   = (float)(n_low - 1);

    // raw Gaussian weights (normalized later over all 31, as reference does)
    if (tid < 31) {
        float e = (float)(tid - 15) / sig;
        w[tid] = expf(-0.5f * e * e);
    }

    // coordinate LUTs (independent of image data)
    for (int i = tid; i < HDIM; i += NT) {
        float p2 = fminf((float)i / res, nl1);      // upsample position
        float l2 = floorf(p2);
        uf[i] = p2 - l2;
        uj[i] = min((int)l2, n_low - 1);
        float pa = fminf((float)i * res, 511.0f);   // downsample position
        float la = floorf(pa);
        df[i] = pa - la;
        dp[i] = (int)la;
    }

    const int base = tile * TW;
    const size_t ib = (size_t)img * HDIM * HDIM;
    const float* ip = x + ib;
    float*       op = out + ib;

    // ---- load slab into A[pos][lane], coalesced either axis ----
    if (ax == 0) {
        for (int idx = tid; idx < HDIM * TW; idx += NT) {
            int lane = idx & (TW - 1);
            int p    = idx >> 4;
            A[p * PITCH + lane] = ip[p * HDIM + base + lane];
        }
    } else {
        int tx = tid & 31, wy = tid >> 5;     // warp strides along pos
        for (int lane = wy; lane < TW; lane += NT / 32)
            for (int p = tx; p < HDIM; p += 32)
                A[p * PITCH + lane] = ip[(base + lane) * HDIM + p];
    }
    __syncthreads();

    // normalization over full 31 taps (redundant per-thread, cheap)
    float inv_wsum = 1.0f;
    if (R > 0) {
        float s = 0.f;
        #pragma unroll
        for (int k = 0; k < 31; k++) s += w[k];
        inv_wsum = 1.0f / s;
    }

    // ---- blur ----
    const float* SRC = A;
    if (R == 3)       { blur_slab<3, 8>(A, S, w, inv_wsum, tid); SRC = S; }
    else if (R == 7)  { blur_slab<7, 8>(A, S, w, inv_wsum, tid); SRC = S; }
    else if (R == 15) { blur_slab<15, 4>(A, S, w, inv_wsum, tid); SRC = S; }
    __syncthreads();

    // ---- downsample: SRC -> LOW (reuse the other buffer) ----
    float* LOW = (R == 0) ? S : A;
    for (int idx = tid; idx < n_low * TW; idx += NT) {
        int lane = idx & (TW - 1);
        int j    = idx >> 4;
        int p1 = dp[j];
        int p2 = min(p1 + 1, HDIM - 1);
        float f = df[j];
        LOW[j * PITCH + lane] = SRC[p1 * PITCH + lane] * (1.0f - f)
                              + SRC[p2 * PITCH + lane] * f;
    }
    __syncthreads();

    // ---- upsample + coalesced store ----
    if (ax == 0) {
        for (int idx = tid; idx < HDIM * TW; idx += NT) {
            int lane = idx & (TW - 1);
            int i    = idx >> 4;
            int j1 = uj[i];
            int j2 = min(j1 + 1, n_low - 1);
            float f = uf[i];
            op[i * HDIM + base + lane] =
                LOW[j1 * PITCH + lane] * (1.0f - f) + LOW[j2 * PITCH + lane] * f;
        }
    } else {
        int tx = tid & 31, wy = tid >> 5;
        for (int i = tx; i < HDIM; i += 32) {
            int j1 = uj[i];
            int j2 = min(j1 + 1, n_low - 1);
            float f = uf[i];
            float omf = 1.0f - f;
            for (int lane = wy; lane < TW; lane += NT / 32)
                op[(base + lane) * HDIM + i] =
                    LOW[j1 * PITCH + lane] * omf + LOW[j2 * PITCH + lane] * f;
        }
    }
}

extern "C" void kernel_launch(void* const* d_in, const int* in_sizes, int n_in,
                              void* d_out, int out_size)
{
    const float* x   = (const float*)d_in[0];
    const float* res = (const float*)d_in[1];
    const int*   ax  = (const int*)d_in[2];
    const float* gp  = (const float*)d_in[3];
    float* out = (float*)d_out;

    const int n_img = in_sizes[1];   // 64
    const size_t smem = (size_t)2 * HDIM * PITCH * sizeof(float);  // 69632 B

    cudaFuncSetAttribute(lowres_kernel,
                         cudaFuncAttributeMaxDynamicSharedMemorySize, (int)smem);

    dim3 grid(HDIM / TW, n_img);     // 32 x 64 = 2048 CTAs
    lowres_kernel<<<grid, NT, smem>>>(x, res, ax, gp, out);
}

// round 5
// speedup vs baseline: 2.0300x; 1.2756x over previous
#include <cuda_runtime.h>
#include <math.h>

// RandomLowRes2D fused kernel, v4: lane-major smem with reflected halo,
// vectorized LDS blur, symmetric register weights, 3 CTAs/SM.

#define HDIM 512
#define TW   8            // lanes (cross-axis) per CTA
#define HALO 16
#define AS   548          // A row stride (floats); 548 % 32 == 4, 16B-aligned rows
#define SP   517          // S/LOW row stride; 517 % 32 == 5 (bijective bank map)
#define NT   256

__device__ __forceinline__ int refl(int t) {
    t = (t < 0) ? (-1 - t) : t;
    return (t >= HDIM) ? (2 * HDIM - 1 - t) : t;
}

// Blur A(+halo, lane-major) -> S along pos. Vec4 window loads, symmetric taps.
template<int R, int UN>
__device__ __forceinline__ void blur_slab(const float* __restrict__ A,
                                          float* __restrict__ S,
                                          const float* __restrict__ w,
                                          float inv_wsum, int tid)
{
    constexpr int LO   = -(((R + 3) / 4) * 4);            // aligned window start
    constexpr int NVEC = (UN - 1 + R - LO) / 4 + 1;       // float4 count
    float wr[R + 1];
    #pragma unroll
    for (int k = 0; k <= R; k++) wr[k] = w[15 - R + k] * inv_wsum;

    for (int task = tid; task < (HDIM / UN) * TW; task += NT) {
        int l  = task & (TW - 1);
        int p0 = (task >> 3) * UN;
        const float4* src = (const float4*)(A + l * AS + HALO + p0 + LO);
        float win[4 * NVEC];
        #pragma unroll
        for (int v = 0; v < NVEC; v++) {
            float4 t4 = src[v];
            win[4*v+0] = t4.x; win[4*v+1] = t4.y;
            win[4*v+2] = t4.z; win[4*v+3] = t4.w;
        }
        float* so = S + l * SP + p0;
        #pragma unroll
        for (int u = 0; u < UN; u++) {
            float acc = wr[R] * win[u - LO];
            #pragma unroll
            for (int k = 0; k < R; k++)
                acc += wr[k] * (win[u - R + k - LO] + win[u + R - k - LO]);
            so[u] = acc;
        }
    }
}

__global__ __launch_bounds__(NT, 3)
void lowres_kernel(const float* __restrict__ x,
                   const float* __restrict__ resolution,
                   const int*   __restrict__ axis,
                   const float* __restrict__ gap,
                   float* __restrict__ out)
{
    extern __shared__ float dynsm[];
    float* A = dynsm;                 // [TW][AS]  input slab + halo (lane-major)
    float* S = dynsm + TW * AS;       // [TW][SP]  blurred slab
    __shared__ float w[32];           // raw Gaussian weights
    __shared__ float uf[HDIM];        // upsample frac per output i
    __shared__ int   uj[HDIM];        // upsample low index per output i
    __shared__ float df[HDIM];        // downsample frac per low j
    __shared__ int   dp[HDIM];        // downsample src row per low j

    const int img  = blockIdx.y;
    const int tile = blockIdx.x;
    const int tid  = threadIdx.x;

    const float res = resolution[img];
    const int   ax  = axis[img];
    const float sig = fmaxf(res * gap[img] * 0.42466090014400953f, 1e-6f);
    const int   R   = (sig < 0.18f) ? 0 : (sig < 0.6f) ? 3 : (sig < 1.4f) ? 7 : 15;

    const int   n_low = (int)fmaxf(floorf(512.0f / res), 1.0f);
    const float nl1   = (float)(n_low - 1);

    if (tid < 31) {
        float e = (float)(tid - 15) / sig;
        w[tid] = expf(-0.5f * e * e);
    }
    for (int i = tid; i < HDIM; i += NT) {
        float p2 = fminf((float)i / res, nl1);
        float l2 = floorf(p2);
        uf[i] = p2 - l2;
        uj[i] = min((int)l2, n_low - 1);
        float pa = fminf((float)i * res, 511.0f);
        float la = floorf(pa);
        df[i] = pa - la;
        dp[i] = (int)la;
    }

    const int base = tile * TW;
    const size_t ib = (size_t)img * HDIM * HDIM;
    const float* ip = x + ib;
    float*       op = out + ib;

    // ---- load slab (float4 gmem) into lane-major A, plus reflected halo ----
    if (ax == 0) {
        const float4* ip4 = (const float4*)ip;
        for (int idx = tid; idx < HDIM * 2; idx += NT) {
            int l4 = idx & 1;          // which float4 within the 8-lane chunk
            int p  = idx >> 1;
            float4 v = ip4[p * (HDIM / 4) + (base >> 2) + l4];
            float* dst = A + (4 * l4) * AS + HALO + p;
            dst[0] = v.x; dst[AS] = v.y; dst[2 * AS] = v.z; dst[3 * AS] = v.w;
        }
    } else {
        for (int idx = tid; idx < TW * (HDIM / 4); idx += NT) {
            int v = idx & 127;
            int l = idx >> 7;
            float4 t = *(const float4*)(ip + (size_t)(base + l) * HDIM + 4 * v);
            *(float4*)(A + l * AS + HALO + 4 * v) = t;
        }
    }
    if (tid < 2 * HALO * TW) {        // 256 halo elements, straight from gmem
        int l = tid & (TW - 1);
        int h = tid >> 3;             // 0..31
        int t = (h < HALO) ? (h - HALO) : (HDIM + h - HALO);
        int rt = refl(t);
        float val = (ax == 0) ? ip[rt * HDIM + base + l]
                              : ip[(size_t)(base + l) * HDIM + rt];
        A[l * AS + HALO + t] = val;
    }
    __syncthreads();

    float inv_wsum = 1.0f;
    if (R > 0) {
        float s = 0.f;
        #pragma unroll
        for (int k = 0; k < 31; k++) s += w[k];
        inv_wsum = 1.0f / s;
    }

    // ---- blur ----
    if      (R == 3)  blur_slab<3, 8>(A, S, w, inv_wsum, tid);
    else if (R == 7)  blur_slab<7, 8>(A, S, w, inv_wsum, tid);
    else if (R == 15) blur_slab<15, 8>(A, S, w, inv_wsum, tid);
    __syncthreads();

    // ---- downsample: SRC -> LOW ----
    const float* SRC = (R > 0) ? S : (A + HALO);
    const int    SST = (R > 0) ? SP : AS;
    float* LOW = (R > 0) ? A : S;     // stride SP; A area (548*8) fits 517*8
    for (int idx = tid; idx < n_low * TW; idx += NT) {
        int l = idx & (TW - 1);
        int j = idx >> 3;
        int p1 = dp[j];
        int p2 = min(p1 + 1, HDIM - 1);
        float f = df[j];
        LOW[l * SP + j] = SRC[l * SST + p1] * (1.0f - f)
                        + SRC[l * SST + p2] * f;
    }
    __syncthreads();

    // ---- upsample + float4 stores ----
    if (ax == 0) {
        for (int idx = tid; idx < HDIM * 2; idx += NT) {
            int l4 = idx & 1;
            int i  = idx >> 1;
            int j1 = uj[i];
            int j2 = min(j1 + 1, n_low - 1);
            float f = uf[i], omf = 1.0f - f;
            const float* L0 = LOW + (4 * l4) * SP;
            float4 r;
            r.x = L0[j1] * omf          + L0[j2] * f;
            r.y = L0[SP + j1] * omf     + L0[SP + j2] * f;
            r.z = L0[2 * SP + j1] * omf + L0[2 * SP + j2] * f;
            r.w = L0[3 * SP + j1] * omf + L0[3 * SP + j2] * f;
            *(float4*)(op + i * HDIM + base + 4 * l4) = r;
        }
    } else {
        for (int idx = tid; idx < TW * (HDIM / 4); idx += NT) {
            int v = idx & 127;
            int l = idx >> 7;
            const float* Lrow = LOW + l * SP;
            float4 r;
            {
                int i = 4 * v;
                int j1 = uj[i], j2 = min(j1 + 1, n_low - 1);
                float f = uf[i];
                r.x = Lrow[j1] * (1.0f - f) + Lrow[j2] * f;
            }
            {
                int i = 4 * v + 1;
                int j1 = uj[i], j2 = min(j1 + 1, n_low - 1);
                float f = uf[i];
                r.y = Lrow[j1] * (1.0f - f) + Lrow[j2] * f;
            }
            {
                int i = 4 * v + 2;
                int j1 = uj[i], j2 = min(j1 + 1, n_low - 1);
                float f = uf[i];
                r.z = Lrow[j1] * (1.0f - f) + Lrow[j2] * f;
            }
            {
                int i = 4 * v + 3;
                int j1 = uj[i], j2 = min(j1 + 1, n_low - 1);
                float f = uf[i];
                r.w = Lrow[j1] * (1.0f - f) + Lrow[j2] * f;
            }
            *(float4*)(op + (size_t)(base + l) * HDIM + 4 * v) = r;
        }
    }
}

extern "C" void kernel_launch(void* const* d_in, const int* in_sizes, int n_in,
                              void* d_out, int out_size)
{
    const float* x   = (const float*)d_in[0];
    const float* res = (const float*)d_in[1];
    const int*   ax  = (const int*)d_in[2];
    const float* gp  = (const float*)d_in[3];
    float* out = (float*)d_out;

    const int n_img = in_sizes[1];   // 64
    const size_t smem = (size_t)(TW * AS + TW * SP) * sizeof(float);  // 34080 B

    cudaFuncSetAttribute(lowres_kernel,
                         cudaFuncAttributeMaxDynamicSharedMemorySize, (int)smem);

    dim3 grid(HDIM / TW, n_img);     // 64 x 64 = 4096 CTAs
    lowres_kernel<<<grid, NT, smem>>>(x, res, ax, gp, out);
}